// round 1
// baseline (speedup 1.0000x reference)
#include <cuda_runtime.h>
#include <cstdint>

typedef unsigned long long u64;

#define Bc 64
#define Tc 512
#define T2c 514
#define Ec 256
#define Hc 256
#define Vc 5000

// scratch activations (allocation-free rule: __device__ globals)
__device__ float g_actA[Bc * Tc * Hc];
__device__ float g_actB[Bc * Tc * Hc];
__device__ float g_pre[Bc * Tc * Hc];

// ---- packed f32x2 helpers (sm_103a FFMA2 path) ----
__device__ __forceinline__ u64 pk2(float x, float y) {
    u64 r; asm("mov.b64 %0,{%1,%2};" : "=l"(r) : "f"(x), "f"(y)); return r;
}
__device__ __forceinline__ u64 fma2(u64 a, u64 b, u64 c) {
    u64 d; asm("fma.rn.f32x2 %0,%1,%2,%3;" : "=l"(d) : "l"(a), "l"(b), "l"(c)); return d;
}
__device__ __forceinline__ float2 up2(u64 p) {
    float2 r; asm("mov.b64 {%0,%1},%2;" : "=f"(r.x), "=f"(r.y) : "l"(p)); return r;
}

// ---- embedding gather: out[b,t,:] = table[x[b,t],:] ----
__global__ void embed_kernel(const int* __restrict__ x, const float* __restrict__ tab,
                             float* __restrict__ out) {
    int bt = blockIdx.x;            // 0 .. B*T-1
    int b = bt >> 9, t = bt & 511;
    int tok = x[b * T2c + t];
    float4 v = reinterpret_cast<const float4*>(tab + (size_t)tok * Ec)[threadIdx.x];
    reinterpret_cast<float4*>(out + (size_t)bt * Ec)[threadIdx.x] = v;
}

// ---- C[m,n] = sum_k A[m,k] * W[n,k] + bias[n]   (A:[M,K] rm, W:[N,K] rm) ----
// 128x128 block tile, 256 threads, 8x8 microtile, f32x2 packed accumulators.
__global__ void __launch_bounds__(256) sgemm_btn(
    const float* __restrict__ A, const float* __restrict__ W,
    const float* __restrict__ bias, float* __restrict__ C,
    int M, int N, int K)
{
    __shared__ __align__(16) float As[16][128];   // [k][m]
    __shared__ __align__(16) float Bs[16][128];   // [k][n]
    int tid = threadIdx.x;
    int m0 = blockIdx.y * 128;
    int n0 = blockIdx.x * 128;
    int tm = (tid >> 4) * 8;
    int tn = (tid & 15) * 8;

    u64 acc[8][4];
#pragma unroll
    for (int i = 0; i < 8; i++)
#pragma unroll
        for (int j = 0; j < 4; j++) acc[i][j] = 0ull;   // bits of {0.f,0.f}

    for (int k0 = 0; k0 < K; k0 += 16) {
#pragma unroll
        for (int half = 0; half < 2; half++) {
            int idx = tid + half * 256;
            int row = idx >> 2;
            int kk = (idx & 3) << 2;
            float4 va = *reinterpret_cast<const float4*>(&A[(size_t)(m0 + row) * K + k0 + kk]);
            As[kk][row] = va.x; As[kk + 1][row] = va.y;
            As[kk + 2][row] = va.z; As[kk + 3][row] = va.w;
            float4 vb = make_float4(0.f, 0.f, 0.f, 0.f);
            if (n0 + row < N)
                vb = *reinterpret_cast<const float4*>(&W[(size_t)(n0 + row) * K + k0 + kk]);
            Bs[kk][row] = vb.x; Bs[kk + 1][row] = vb.y;
            Bs[kk + 2][row] = vb.z; Bs[kk + 3][row] = vb.w;
        }
        __syncthreads();
#pragma unroll
        for (int k = 0; k < 16; k++) {
            float a[8];
            *reinterpret_cast<float4*>(a) = *reinterpret_cast<const float4*>(&As[k][tm]);
            *reinterpret_cast<float4*>(a + 4) = *reinterpret_cast<const float4*>(&As[k][tm + 4]);
            ulonglong2 b0 = *reinterpret_cast<const ulonglong2*>(&Bs[k][tn]);
            ulonglong2 b1 = *reinterpret_cast<const ulonglong2*>(&Bs[k][tn + 4]);
            u64 bb0 = b0.x, bb1 = b0.y, bb2 = b1.x, bb3 = b1.y;
#pragma unroll
            for (int i = 0; i < 8; i++) {
                u64 ad = pk2(a[i], a[i]);
                acc[i][0] = fma2(ad, bb0, acc[i][0]);
                acc[i][1] = fma2(ad, bb1, acc[i][1]);
                acc[i][2] = fma2(ad, bb2, acc[i][2]);
                acc[i][3] = fma2(ad, bb3, acc[i][3]);
            }
        }
        __syncthreads();
    }
#pragma unroll
    for (int i = 0; i < 8; i++) {
        int m = m0 + tm + i;
#pragma unroll
        for (int j = 0; j < 4; j++) {
            int n = n0 + tn + j * 2;
            float2 v = up2(acc[i][j]);
            if (n < N)     C[(size_t)m * N + n]     = v.x + bias[n];
            if (n + 1 < N) C[(size_t)m * N + n + 1] = v.y + bias[n + 1];
        }
    }
}

// ---- recurrence: h_t = tanh(pre[t] + Whh @ h_{t-1} + bhh), one CTA per batch ----
// Whh row r: k=[0,128) in smem (float4, [k4][r] transposed layout, conflict-free),
//            k=[128,256) in 128 registers per thread. All math via f32x2 FMA.
#define SCAN_W4 32                                       // k4 chunks in smem (k = 0..127)
#define SCAN_SMEM (SCAN_W4 * 256 * 16 + 256 * 4)
__global__ void __launch_bounds__(256, 1) rnn_scan(
    const float* __restrict__ pre, const float* __restrict__ Whh,
    const float* __restrict__ bhh, float* __restrict__ out, float* __restrict__ hlast)
{
    extern __shared__ __align__(16) float sm[];
    float4* w4 = reinterpret_cast<float4*>(sm);          // [k4*256 + r]
    float* h_s = sm + SCAN_W4 * 256 * 4;                 // 256 floats
    int b = blockIdx.x, r = threadIdx.x;

#pragma unroll
    for (int k4 = 0; k4 < SCAN_W4; k4++)
        w4[k4 * 256 + r] = *reinterpret_cast<const float4*>(&Whh[r * 256 + k4 * 4]);

    u64 wreg[64];                                        // k = 128..255 packed pairs
#pragma unroll
    for (int i = 0; i < 32; i++) {
        ulonglong2 v = *reinterpret_cast<const ulonglong2*>(&Whh[r * 256 + 128 + i * 4]);
        wreg[2 * i] = v.x; wreg[2 * i + 1] = v.y;
    }
    float bias = bhh[r];
    h_s[r] = 0.f;
    __syncthreads();

    const float* preb = pre + (size_t)b * Tc * Hc;
    float* outb = out + (size_t)b * Tc * Hc;
    const ulonglong2* w2s = reinterpret_cast<const ulonglong2*>(sm);
    const ulonglong2* h2s = reinterpret_cast<const ulonglong2*>(h_s);

    float hn = 0.f;
    for (int t = 0; t < Tc; t++) {
        u64 acc = pk2(preb[t * Hc + r] + bias, 0.f);
#pragma unroll
        for (int k4 = 0; k4 < SCAN_W4; k4++) {
            ulonglong2 w = w2s[k4 * 256 + r];
            ulonglong2 h = h2s[k4];
            acc = fma2(w.x, h.x, acc);
            acc = fma2(w.y, h.y, acc);
        }
#pragma unroll
        for (int k4 = 0; k4 < 32; k4++) {
            ulonglong2 h = h2s[32 + k4];
            acc = fma2(wreg[2 * k4], h.x, acc);
            acc = fma2(wreg[2 * k4 + 1], h.y, acc);
        }
        float2 p = up2(acc);
        hn = tanhf(p.x + p.y);
        __syncthreads();          // all reads of h_s done
        h_s[r] = hn;
        outb[t * Hc + r] = hn;
        __syncthreads();          // h_s updated for next step
    }
    hlast[b * Hc + r] = hn;
}

// ---- seq_len passthrough: out[i] = (float)x[i, 513] ----
__global__ void tail_kernel(const int* __restrict__ x, float* __restrict__ outSeq) {
    int i = threadIdx.x;
    outSeq[i] = (float)x[i * T2c + (T2c - 1)];
}

extern "C" void kernel_launch(void* const* d_in, const int* in_sizes, int n_in,
                              void* d_out, int out_size) {
    const int*   x    = (const int*)d_in[0];
    const float* tab  = (const float*)d_in[1];
    const float* Wih  = (const float*)d_in[2];   // [2,256,256]
    const float* Whh  = (const float*)d_in[3];   // [2,256,256]
    const float* bih  = (const float*)d_in[4];   // [2,256]
    const float* bhh  = (const float*)d_in[5];   // [2,256]
    const float* Wout = (const float*)d_in[6];   // [5000,256]
    const float* bout = (const float*)d_in[7];   // [5000]
    float* out = (float*)d_out;

    float *actA, *actB, *pre;
    cudaGetSymbolAddress((void**)&actA, g_actA);
    cudaGetSymbolAddress((void**)&actB, g_actB);
    cudaGetSymbolAddress((void**)&pre, g_pre);

    cudaFuncSetAttribute(rnn_scan, cudaFuncAttributeMaxDynamicSharedMemorySize, SCAN_SMEM);

    const size_t LOGITS = (size_t)Bc * Tc * Vc;          // 163,840,000
    float* lstate = out + LOGITS;                        // [2,64,256]
    float* seq = out + LOGITS + 2 * Bc * Hc;             // [64]

    embed_kernel<<<Bc * Tc, 64>>>(x, tab, actA);

    dim3 blk(256);
    dim3 gpre(2, 256);   // N=256 -> 2 col blocks, M=32768 -> 256 row blocks
    // layer 0
    sgemm_btn<<<gpre, blk>>>(actA, Wih, bih, pre, Bc * Tc, Hc, Ec);
    rnn_scan<<<Bc, 256, SCAN_SMEM>>>(pre, Whh, bhh, actB, lstate);
    // layer 1
    sgemm_btn<<<gpre, blk>>>(actB, Wih + Hc * Ec, bih + Hc, pre, Bc * Tc, Hc, Hc);
    rnn_scan<<<Bc, 256, SCAN_SMEM>>>(pre, Whh + Hc * Hc, bhh + Hc, actA, lstate + Bc * Hc);
    // output projection
    dim3 gout((Vc + 127) / 128, 256);
    sgemm_btn<<<gout, blk>>>(actA, Wout, bout, out, Bc * Tc, Vc, Hc);

    tail_kernel<<<1, Bc>>>(x, seq);
}

// round 3
// speedup vs baseline: 1.6099x; 1.6099x over previous
#include <cuda_runtime.h>
#include <cuda_bf16.h>
#include <cstdint>

typedef unsigned long long u64;
typedef unsigned int u32;

#define Bc 64
#define Tc 512
#define T2c 514
#define Ec 256
#define Hc 256
#define Vc 5000

// scratch (allocation-free rule: __device__ globals)
__device__ float g_actA[Bc * Tc * Hc];
__device__ float g_actB[Bc * Tc * Hc];
__device__ float g_pre[Bc * Tc * Hc];
__device__ __nv_bfloat16 g_ahi[Bc * Tc * Hc];
__device__ __nv_bfloat16 g_alo[Bc * Tc * Hc];
__device__ __nv_bfloat16 g_whi[Vc * Hc];
__device__ __nv_bfloat16 g_wlo[Vc * Hc];

// ---------------- helpers ----------------
__device__ __forceinline__ u32 smem_u32(const void* p) {
    u32 a; asm("{ .reg .u64 t; cvta.to.shared.u64 t, %1; cvt.u32.u64 %0, t; }" : "=r"(a) : "l"(p));
    return a;
}
__device__ __forceinline__ u64 pk2(float x, float y) {
    u64 r; asm("mov.b64 %0,{%1,%2};" : "=l"(r) : "f"(x), "f"(y)); return r;
}
__device__ __forceinline__ u64 fma2(u64 a, u64 b, u64 c) {
    u64 d; asm("fma.rn.f32x2 %0,%1,%2,%3;" : "=l"(d) : "l"(a), "l"(b), "l"(c)); return d;
}
__device__ __forceinline__ float2 up2(u64 p) {
    float2 r; asm("mov.b64 {%0,%1},%2;" : "=f"(r.x), "=f"(r.y) : "l"(p)); return r;
}
__device__ __forceinline__ void ldsm_x4(u32* r, u32 addr) {
    asm volatile("ldmatrix.sync.aligned.m8n8.x4.shared.b16 {%0,%1,%2,%3}, [%4];"
                 : "=r"(r[0]), "=r"(r[1]), "=r"(r[2]), "=r"(r[3]) : "r"(addr));
}
__device__ __forceinline__ void ldsm_x2(u32* r, u32 addr) {
    asm volatile("ldmatrix.sync.aligned.m8n8.x2.shared.b16 {%0,%1}, [%2];"
                 : "=r"(r[0]), "=r"(r[1]) : "r"(addr));
}
__device__ __forceinline__ void mma_bf16(float* d, const u32* a, const u32* b) {
    asm volatile(
        "mma.sync.aligned.m16n8k16.row.col.f32.bf16.bf16.f32 "
        "{%0,%1,%2,%3},{%4,%5,%6,%7},{%8,%9},{%0,%1,%2,%3};"
        : "+f"(d[0]), "+f"(d[1]), "+f"(d[2]), "+f"(d[3])
        : "r"(a[0]), "r"(a[1]), "r"(a[2]), "r"(a[3]), "r"(b[0]), "r"(b[1]));
}

// ---------------- embedding gather ----------------
__global__ void embed_kernel(const int* __restrict__ x, const float* __restrict__ tab,
                             float* __restrict__ out) {
    int bt = blockIdx.x;
    int b = bt >> 9, t = bt & 511;
    int tok = x[b * T2c + t];
    float4 v = reinterpret_cast<const float4*>(tab + (size_t)tok * Ec)[threadIdx.x];
    reinterpret_cast<float4*>(out + (size_t)bt * Ec)[threadIdx.x] = v;
}

// ---------------- fp32 -> (hi, lo) bf16 split ----------------
__global__ void conv_kernel(const float* __restrict__ src,
                            __nv_bfloat16* __restrict__ hi, __nv_bfloat16* __restrict__ lo) {
    size_t i = ((size_t)blockIdx.x * 256 + threadIdx.x) * 4;
    float4 v = *reinterpret_cast<const float4*>(src + i);
    __nv_bfloat16 h0 = __float2bfloat16(v.x), h1 = __float2bfloat16(v.y);
    __nv_bfloat16 h2 = __float2bfloat16(v.z), h3 = __float2bfloat16(v.w);
    __nv_bfloat16 l0 = __float2bfloat16(v.x - __bfloat162float(h0));
    __nv_bfloat16 l1 = __float2bfloat16(v.y - __bfloat162float(h1));
    __nv_bfloat16 l2 = __float2bfloat16(v.z - __bfloat162float(h2));
    __nv_bfloat16 l3 = __float2bfloat16(v.w - __bfloat162float(h3));
    *reinterpret_cast<ushort4*>(hi + i) = make_ushort4(
        __bfloat16_as_ushort(h0), __bfloat16_as_ushort(h1),
        __bfloat16_as_ushort(h2), __bfloat16_as_ushort(h3));
    *reinterpret_cast<ushort4*>(lo + i) = make_ushort4(
        __bfloat16_as_ushort(l0), __bfloat16_as_ushort(l1),
        __bfloat16_as_ushort(l2), __bfloat16_as_ushort(l3));
}

// ---------------- HMMA split-bf16 GEMM ----------------
// C[m,n] = sum_k A[m,k]*W[n,k] + bias[n]; 3 passes: Ahi*Bhi + Ahi*Blo + Alo*Bhi.
// CTA 128x128, warps 2(M) x 4(N), warp tile 64x32. smem stride 40 bf16 (80B) -> LDSM conflict-free.
#define AS_STRIDE 40
__global__ void __launch_bounds__(256, 2) mma_gemm(
    const __nv_bfloat16* __restrict__ Ahi, const __nv_bfloat16* __restrict__ Alo,
    const __nv_bfloat16* __restrict__ Bhi, const __nv_bfloat16* __restrict__ Blo,
    const float* __restrict__ bias, float* __restrict__ C, int Nact)
{
    __shared__ __align__(16) __nv_bfloat16 A_s[128 * AS_STRIDE];
    __shared__ __align__(16) __nv_bfloat16 B_s[128 * AS_STRIDE];
    const int tid = threadIdx.x;
    const int wid = tid >> 5, lane = tid & 31;
    const int m0 = blockIdx.y * 128, n0 = blockIdx.x * 128;
    const int wm = (wid >> 2) * 64, wn = (wid & 3) * 32;

    const u32 sa = smem_u32(A_s), sbm = smem_u32(B_s);
    // ldmatrix lane addresses (bytes)
    const u32 aAddr0 = sa + ((wm + (lane & 15)) * AS_STRIDE) * 2 + (lane >> 4) * 16;
    const u32 bAddr0 = sbm + ((wn + (lane & 7)) * AS_STRIDE) * 2 + ((lane >> 3) & 1) * 16;

    float acc[4][4][4];
#pragma unroll
    for (int i = 0; i < 4; i++)
#pragma unroll
        for (int j = 0; j < 4; j++)
#pragma unroll
            for (int q = 0; q < 4; q++) acc[i][j][q] = 0.f;

#pragma unroll 1
    for (int pass = 0; pass < 3; pass++) {
        const __nv_bfloat16* Ap = (pass == 2) ? Alo : Ahi;
        const __nv_bfloat16* Bp = (pass == 1) ? Blo : Bhi;
#pragma unroll 1
        for (int k0 = 0; k0 < 256; k0 += 32) {
            __syncthreads();
#pragma unroll
            for (int i = 0; i < 2; i++) {
                int v = tid + i * 256;              // 0..511
                int row = v >> 2, kc = (v & 3) * 8;
                uint4 va = *reinterpret_cast<const uint4*>(Ap + (size_t)(m0 + row) * 256 + k0 + kc);
                *reinterpret_cast<uint4*>(&A_s[row * AS_STRIDE + kc]) = va;
                uint4 vb = make_uint4(0, 0, 0, 0);
                if (n0 + row < Nact)
                    vb = *reinterpret_cast<const uint4*>(Bp + (size_t)(n0 + row) * 256 + k0 + kc);
                *reinterpret_cast<uint4*>(&B_s[row * AS_STRIDE + kc]) = vb;
            }
            __syncthreads();
#pragma unroll
            for (int kk = 0; kk < 2; kk++) {
                u32 af[4][4], bf[4][2];
#pragma unroll
                for (int im = 0; im < 4; im++)
                    ldsm_x4(af[im], aAddr0 + im * 16 * AS_STRIDE * 2 + kk * 32);
#pragma unroll
                for (int jn = 0; jn < 4; jn++)
                    ldsm_x2(bf[jn], bAddr0 + jn * 8 * AS_STRIDE * 2 + kk * 32);
#pragma unroll
                for (int im = 0; im < 4; im++)
#pragma unroll
                    for (int jn = 0; jn < 4; jn++)
                        mma_bf16(acc[im][jn], af[im], bf[jn]);
            }
        }
    }

    // epilogue
    const int rbase = m0 + wm + (lane >> 2);
    const int cbase = n0 + wn + (lane & 3) * 2;
#pragma unroll
    for (int im = 0; im < 4; im++) {
#pragma unroll
        for (int jn = 0; jn < 4; jn++) {
            int n = cbase + jn * 8;
            if (n < Nact) {
                float bx = bias[n], by = bias[n + 1];
                int r0 = rbase + im * 16;
                *reinterpret_cast<float2*>(C + (size_t)r0 * Nact + n) =
                    make_float2(acc[im][jn][0] + bx, acc[im][jn][1] + by);
                *reinterpret_cast<float2*>(C + (size_t)(r0 + 8) * Nact + n) =
                    make_float2(acc[im][jn][2] + bx, acc[im][jn][3] + by);
            }
        }
    }
}

// ---------------- recurrence ----------------
#define SCAN_W4 32
#define SCAN_SMEM (SCAN_W4 * 256 * 16 + 256 * 4)
__global__ void __launch_bounds__(256, 1) rnn_scan(
    const float* __restrict__ pre, const float* __restrict__ Whh,
    const float* __restrict__ bhh, float* __restrict__ out, float* __restrict__ hlast)
{
    extern __shared__ __align__(16) float sm[];
    float4* w4 = reinterpret_cast<float4*>(sm);
    float* h_s = sm + SCAN_W4 * 256 * 4;
    int b = blockIdx.x, r = threadIdx.x;

#pragma unroll
    for (int k4 = 0; k4 < SCAN_W4; k4++)
        w4[k4 * 256 + r] = *reinterpret_cast<const float4*>(&Whh[r * 256 + k4 * 4]);

    u64 wreg[64];
#pragma unroll
    for (int i = 0; i < 32; i++) {
        ulonglong2 v = *reinterpret_cast<const ulonglong2*>(&Whh[r * 256 + 128 + i * 4]);
        wreg[2 * i] = v.x; wreg[2 * i + 1] = v.y;
    }
    float bias = bhh[r];
    h_s[r] = 0.f;
    __syncthreads();

    const float* preb = pre + (size_t)b * Tc * Hc;
    float* outb = out + (size_t)b * Tc * Hc;
    const ulonglong2* w2s = reinterpret_cast<const ulonglong2*>(sm);
    const ulonglong2* h2s = reinterpret_cast<const ulonglong2*>(h_s);

    float hn = 0.f;
    for (int t = 0; t < Tc; t++) {
        u64 acc = pk2(preb[t * Hc + r] + bias, 0.f);
#pragma unroll
        for (int k4 = 0; k4 < SCAN_W4; k4++) {
            ulonglong2 w = w2s[k4 * 256 + r];
            ulonglong2 h = h2s[k4];
            acc = fma2(w.x, h.x, acc);
            acc = fma2(w.y, h.y, acc);
        }
#pragma unroll
        for (int k4 = 0; k4 < 32; k4++) {
            ulonglong2 h = h2s[32 + k4];
            acc = fma2(wreg[2 * k4], h.x, acc);
            acc = fma2(wreg[2 * k4 + 1], h.y, acc);
        }
        float2 p = up2(acc);
        hn = tanhf(p.x + p.y);
        __syncthreads();
        h_s[r] = hn;
        outb[t * Hc + r] = hn;
        __syncthreads();
    }
    hlast[b * Hc + r] = hn;
}

__global__ void tail_kernel(const int* __restrict__ x, float* __restrict__ outSeq) {
    int i = threadIdx.x;
    outSeq[i] = (float)x[i * T2c + (T2c - 1)];
}

extern "C" void kernel_launch(void* const* d_in, const int* in_sizes, int n_in,
                              void* d_out, int out_size) {
    const int*   x    = (const int*)d_in[0];
    const float* tab  = (const float*)d_in[1];
    const float* Wih  = (const float*)d_in[2];
    const float* Whh  = (const float*)d_in[3];
    const float* bih  = (const float*)d_in[4];
    const float* bhh  = (const float*)d_in[5];
    const float* Wout = (const float*)d_in[6];
    const float* bout = (const float*)d_in[7];
    float* out = (float*)d_out;

    float *actA, *actB, *pre;
    __nv_bfloat16 *ahi, *alo, *whi, *wlo;
    cudaGetSymbolAddress((void**)&actA, g_actA);
    cudaGetSymbolAddress((void**)&actB, g_actB);
    cudaGetSymbolAddress((void**)&pre, g_pre);
    cudaGetSymbolAddress((void**)&ahi, g_ahi);
    cudaGetSymbolAddress((void**)&alo, g_alo);
    cudaGetSymbolAddress((void**)&whi, g_whi);
    cudaGetSymbolAddress((void**)&wlo, g_wlo);

    cudaFuncSetAttribute(rnn_scan, cudaFuncAttributeMaxDynamicSharedMemorySize, SCAN_SMEM);

    const size_t LOGITS = (size_t)Bc * Tc * Vc;
    float* lstate = out + LOGITS;
    float* seq = out + LOGITS + 2 * Bc * Hc;

    const int CONV_ACT = (Bc * Tc * Hc) / 1024;   // 16384 blocks
    const int CONV_LW = (Hc * Ec) / 1024;         // 64 blocks
    const int CONV_WOUT = (Vc * Hc) / 1024;       // 1250 blocks

    embed_kernel<<<Bc * Tc, 64>>>(x, tab, actA);

    dim3 blk(256);
    // layer 0
    conv_kernel<<<CONV_ACT, 256>>>(actA, ahi, alo);
    conv_kernel<<<CONV_LW, 256>>>(Wih, whi, wlo);
    mma_gemm<<<dim3(2, 256), blk>>>(ahi, alo, whi, wlo, bih, pre, Hc);
    rnn_scan<<<Bc, 256, SCAN_SMEM>>>(pre, Whh, bhh, actB, lstate);
    // layer 1
    conv_kernel<<<CONV_ACT, 256>>>(actB, ahi, alo);
    conv_kernel<<<CONV_LW, 256>>>(Wih + Hc * Ec, whi, wlo);
    mma_gemm<<<dim3(2, 256), blk>>>(ahi, alo, whi, wlo, bih + Hc, pre, Hc);
    rnn_scan<<<Bc, 256, SCAN_SMEM>>>(pre, Whh + Hc * Hc, bhh + Hc, actA, lstate + Bc * Hc);
    // output projection
    conv_kernel<<<CONV_ACT, 256>>>(actA, ahi, alo);
    conv_kernel<<<CONV_WOUT, 256>>>(Wout, whi, wlo);
    mma_gemm<<<dim3((Vc + 127) / 128, 256), blk>>>(ahi, alo, whi, wlo, bout, out, Vc);

    tail_kernel<<<1, Bc>>>(x, seq);
}

// round 4
// speedup vs baseline: 2.1229x; 1.3187x over previous
#include <cuda_runtime.h>
#include <cuda_bf16.h>
#include <cstdint>

typedef unsigned long long u64;
typedef unsigned int u32;

#define Bc 64
#define Tc 512
#define T2c 514
#define Ec 256
#define Hc 256
#define Vc 5000

// scratch (allocation-free rule: __device__ globals)
__device__ float g_actA[Bc * Tc * Hc];
__device__ float g_actB[Bc * Tc * Hc];
__device__ float g_pre[Bc * Tc * Hc];
__device__ __nv_bfloat16 g_ahi[Bc * Tc * Hc];
__device__ __nv_bfloat16 g_alo[Bc * Tc * Hc];
__device__ __nv_bfloat16 g_whi[Vc * Hc];
__device__ __nv_bfloat16 g_wlo[Vc * Hc];

// ---------------- helpers ----------------
__device__ __forceinline__ u32 smem_u32(const void* p) {
    u32 a; asm("{ .reg .u64 t; cvta.to.shared.u64 t, %1; cvt.u32.u64 %0, t; }" : "=r"(a) : "l"(p));
    return a;
}
__device__ __forceinline__ u64 pk2(float x, float y) {
    u64 r; asm("mov.b64 %0,{%1,%2};" : "=l"(r) : "f"(x), "f"(y)); return r;
}
__device__ __forceinline__ u64 fma2(u64 a, u64 b, u64 c) {
    u64 d; asm("fma.rn.f32x2 %0,%1,%2,%3;" : "=l"(d) : "l"(a), "l"(b), "l"(c)); return d;
}
__device__ __forceinline__ float2 up2(u64 p) {
    float2 r; asm("mov.b64 {%0,%1},%2;" : "=f"(r.x), "=f"(r.y) : "l"(p)); return r;
}
__device__ __forceinline__ void ldsm_x4(u32* r, u32 addr) {
    asm volatile("ldmatrix.sync.aligned.m8n8.x4.shared.b16 {%0,%1,%2,%3}, [%4];"
                 : "=r"(r[0]), "=r"(r[1]), "=r"(r[2]), "=r"(r[3]) : "r"(addr));
}
__device__ __forceinline__ void ldsm_x2(u32* r, u32 addr) {
    asm volatile("ldmatrix.sync.aligned.m8n8.x2.shared.b16 {%0,%1}, [%2];"
                 : "=r"(r[0]), "=r"(r[1]) : "r"(addr));
}
__device__ __forceinline__ void mma_bf16(float* d, const u32* a, const u32* b) {
    asm volatile(
        "mma.sync.aligned.m16n8k16.row.col.f32.bf16.bf16.f32 "
        "{%0,%1,%2,%3},{%4,%5,%6,%7},{%8,%9},{%0,%1,%2,%3};"
        : "+f"(d[0]), "+f"(d[1]), "+f"(d[2]), "+f"(d[3])
        : "r"(a[0]), "r"(a[1]), "r"(a[2]), "r"(a[3]), "r"(b[0]), "r"(b[1]));
}
__device__ __forceinline__ void cpa16(u32 dst, const void* src, u32 sz) {
    asm volatile("cp.async.cg.shared.global [%0], [%1], 16, %2;"
                 :: "r"(dst), "l"(src), "r"(sz) : "memory");
}
__device__ __forceinline__ void cp_commit() {
    asm volatile("cp.async.commit_group;" ::: "memory");
}
__device__ __forceinline__ float tanh_acc(float x) {
    float ax = fabsf(x);
    float e;
    asm("ex2.approx.f32 %0, %1;" : "=f"(e) : "f"(-2.885390082f * ax)); // exp(-2|x|)
    float denom;
    asm("rcp.approx.f32 %0, %1;" : "=f"(denom) : "f"(1.0f + e));
    float t = (1.0f - e) * denom;
    return copysignf(t, x);
}

// ---------------- embedding gather ----------------
__global__ void embed_kernel(const int* __restrict__ x, const float* __restrict__ tab,
                             float* __restrict__ out) {
    int bt = blockIdx.x;
    int b = bt >> 9, t = bt & 511;
    int tok = x[b * T2c + t];
    float4 v = reinterpret_cast<const float4*>(tab + (size_t)tok * Ec)[threadIdx.x];
    reinterpret_cast<float4*>(out + (size_t)bt * Ec)[threadIdx.x] = v;
}

// ---------------- fp32 -> (hi, lo) bf16 split ----------------
__global__ void conv_kernel(const float* __restrict__ src,
                            __nv_bfloat16* __restrict__ hi, __nv_bfloat16* __restrict__ lo) {
    size_t i = ((size_t)blockIdx.x * 256 + threadIdx.x) * 4;
    float4 v = *reinterpret_cast<const float4*>(src + i);
    __nv_bfloat16 h0 = __float2bfloat16(v.x), h1 = __float2bfloat16(v.y);
    __nv_bfloat16 h2 = __float2bfloat16(v.z), h3 = __float2bfloat16(v.w);
    __nv_bfloat16 l0 = __float2bfloat16(v.x - __bfloat162float(h0));
    __nv_bfloat16 l1 = __float2bfloat16(v.y - __bfloat162float(h1));
    __nv_bfloat16 l2 = __float2bfloat16(v.z - __bfloat162float(h2));
    __nv_bfloat16 l3 = __float2bfloat16(v.w - __bfloat162float(h3));
    *reinterpret_cast<ushort4*>(hi + i) = make_ushort4(
        __bfloat16_as_ushort(h0), __bfloat16_as_ushort(h1),
        __bfloat16_as_ushort(h2), __bfloat16_as_ushort(h3));
    *reinterpret_cast<ushort4*>(lo + i) = make_ushort4(
        __bfloat16_as_ushort(l0), __bfloat16_as_ushort(l1),
        __bfloat16_as_ushort(l2), __bfloat16_as_ushort(l3));
}

// ---------------- HMMA split-bf16 GEMM v2 ----------------
// C = A*W^T + bias; 3 products Ahi*Bhi + Ahi*Blo + Alo*Bhi accumulated in one acc.
// All 4 operand tiles loaded once per k-chunk via cp.async, double-buffered.
// CTA 128x128, warps 2(M)x4(N), warp tile 64x32. Row stride 40 bf16 (80B): LDSM conflict-free.
#define TILE_B 10240            // 128 rows * 80 bytes
#define STAGE_B (4 * TILE_B)    // Ahi|Alo|Bhi|Blo
#define GEMM_SMEM (2 * STAGE_B) // 81920

__global__ void __launch_bounds__(256, 2) mma_gemm(
    const __nv_bfloat16* __restrict__ Ahi, const __nv_bfloat16* __restrict__ Alo,
    const __nv_bfloat16* __restrict__ Bhi, const __nv_bfloat16* __restrict__ Blo,
    const float* __restrict__ bias, float* __restrict__ C, int Nact)
{
    extern __shared__ __align__(16) char smem[];
    const u32 sb = smem_u32(smem);
    const int tid = threadIdx.x;
    const int wid = tid >> 5, lane = tid & 31;
    const int m0 = blockIdx.y * 128, n0 = blockIdx.x * 128;
    const int wm = (wid >> 2) * 64, wn = (wid & 3) * 32;

    // per-thread load slots: u in {tid, tid+256}; row=u>>2, seg=u&3 (16B segs)
    const int row0 = tid >> 2, seg0 = tid & 3;
    const int row1 = (tid + 256) >> 2, seg1 = (tid + 256) & 3;

    float acc[4][4][4];
#pragma unroll
    for (int i = 0; i < 4; i++)
#pragma unroll
        for (int j = 0; j < 4; j++)
#pragma unroll
            for (int q = 0; q < 4; q++) acc[i][j][q] = 0.f;

    auto load_chunk = [&](int k0, int stage) {
        const u32 base = sb + stage * STAGE_B;
#pragma unroll
        for (int h = 0; h < 2; h++) {
            const int row = h ? row1 : row0;
            const int seg = h ? seg1 : seg0;
            const u32 dst = base + row * 80 + seg * 16;
            const size_t aoff = (size_t)(m0 + row) * 256 + k0 + seg * 8;
            cpa16(dst, Ahi + aoff, 16);
            cpa16(dst + TILE_B, Alo + aoff, 16);
            const int br = n0 + row;
            const u32 sz = (br < Nact) ? 16u : 0u;
            const int brc = (br < Nact) ? br : (Nact - 1);
            const size_t boff = (size_t)brc * 256 + k0 + seg * 8;
            cpa16(dst + 2 * TILE_B, Bhi + boff, sz);
            cpa16(dst + 3 * TILE_B, Blo + boff, sz);
        }
        cp_commit();
    };

    const u32 arow = (wm + (lane & 15)) * 80 + (lane >> 4) * 16;
    const u32 brow = (wn + (lane & 7)) * 80 + ((lane >> 3) & 1) * 16;

    load_chunk(0, 0);

#pragma unroll 1
    for (int ic = 0; ic < 8; ic++) {
        if (ic < 7) load_chunk((ic + 1) * 32, (ic + 1) & 1);
        if (ic < 7) asm volatile("cp.async.wait_group 1;" ::: "memory");
        else        asm volatile("cp.async.wait_group 0;" ::: "memory");
        __syncthreads();

        const u32 base = sb + (ic & 1) * STAGE_B;
        const u32 aHi = base, aLo = base + TILE_B, bHi = base + 2 * TILE_B, bLo = base + 3 * TILE_B;
#pragma unroll
        for (int kk = 0; kk < 2; kk++) {
            u32 af[4][4], bh[4][2], bl[4][2];
#pragma unroll
            for (int im = 0; im < 4; im++)
                ldsm_x4(af[im], aHi + arow + im * 16 * 80 + kk * 32);
#pragma unroll
            for (int jn = 0; jn < 4; jn++) {
                ldsm_x2(bh[jn], bHi + brow + jn * 8 * 80 + kk * 32);
                ldsm_x2(bl[jn], bLo + brow + jn * 8 * 80 + kk * 32);
            }
#pragma unroll
            for (int im = 0; im < 4; im++)
#pragma unroll
                for (int jn = 0; jn < 4; jn++)
                    mma_bf16(acc[im][jn], af[im], bh[jn]);
#pragma unroll
            for (int im = 0; im < 4; im++)
#pragma unroll
                for (int jn = 0; jn < 4; jn++)
                    mma_bf16(acc[im][jn], af[im], bl[jn]);
#pragma unroll
            for (int im = 0; im < 4; im++)
                ldsm_x4(af[im], aLo + arow + im * 16 * 80 + kk * 32);
#pragma unroll
            for (int im = 0; im < 4; im++)
#pragma unroll
                for (int jn = 0; jn < 4; jn++)
                    mma_bf16(acc[im][jn], af[im], bh[jn]);
        }
        __syncthreads();
    }

    // epilogue
    const int rbase = m0 + wm + (lane >> 2);
    const int cbase = n0 + wn + (lane & 3) * 2;
#pragma unroll
    for (int im = 0; im < 4; im++) {
#pragma unroll
        for (int jn = 0; jn < 4; jn++) {
            int n = cbase + jn * 8;
            if (n < Nact) {
                float bx = bias[n], by = bias[n + 1];
                int r0 = rbase + im * 16;
                *reinterpret_cast<float2*>(C + (size_t)r0 * Nact + n) =
                    make_float2(acc[im][jn][0] + bx, acc[im][jn][1] + by);
                *reinterpret_cast<float2*>(C + (size_t)(r0 + 8) * Nact + n) =
                    make_float2(acc[im][jn][2] + bx, acc[im][jn][3] + by);
            }
        }
    }
}

// ---------------- recurrence v2 ----------------
// h_t = tanh(pre[t] + Whh h_{t-1} + b). 1 CTA/batch, 256 threads (1 row each).
// k=[0,64) weights in smem ([k4][r] transposed, conflict-free LDS.128);
// k=[64,256) weights in 96 u64 registers. h double-buffered in smem -> 1 barrier/step.
// pre[t+1] prefetched. tanh via ex2/rcp approx (~1e-6 rel err).
#define KS4 16
#define SCAN_SMEM (KS4 * 256 * 16 + 2 * 256 * 4)
__global__ void __launch_bounds__(256, 1) rnn_scan(
    const float* __restrict__ pre, const float* __restrict__ Whh,
    const float* __restrict__ bhh, float* __restrict__ out, float* __restrict__ hlast)
{
    extern __shared__ __align__(16) float sm[];
    float4* w4 = reinterpret_cast<float4*>(sm);          // KS4*256 float4
    float* hbuf = sm + KS4 * 256 * 4;                    // 2 x 256 floats
    const int b = blockIdx.x, r = threadIdx.x;

#pragma unroll
    for (int k4 = 0; k4 < KS4; k4++)
        w4[k4 * 256 + r] = *reinterpret_cast<const float4*>(&Whh[r * 256 + k4 * 4]);

    u64 wreg[96];                                        // k = 64..255
#pragma unroll
    for (int j = 0; j < 48; j++) {
        ulonglong2 v = *reinterpret_cast<const ulonglong2*>(&Whh[r * 256 + 64 + j * 4]);
        wreg[2 * j] = v.x; wreg[2 * j + 1] = v.y;
    }
    const float bias = bhh[r];
    hbuf[r] = 0.f;
    __syncthreads();

    const float* preb = pre + (size_t)b * Tc * Hc;
    float* outb = out + (size_t)b * Tc * Hc;
    const ulonglong2* w2s = reinterpret_cast<const ulonglong2*>(sm);

    float pc = preb[r];
    float hn = 0.f;
#pragma unroll 1
    for (int t = 0; t < Tc; t++) {
        int tn = (t + 1 < Tc) ? t + 1 : t;
        float pn = preb[tn * Hc + r];                    // prefetch next step
        const ulonglong2* hc = reinterpret_cast<const ulonglong2*>(hbuf + (t & 1) * 256);
        u64 acc = pk2(pc + bias, 0.f);
#pragma unroll
        for (int k4 = 0; k4 < KS4; k4++) {
            ulonglong2 w = w2s[k4 * 256 + r];
            ulonglong2 h = hc[k4];
            acc = fma2(w.x, h.x, acc);
            acc = fma2(w.y, h.y, acc);
        }
#pragma unroll
        for (int j = 0; j < 48; j++) {
            ulonglong2 h = hc[KS4 + j];
            acc = fma2(wreg[2 * j], h.x, acc);
            acc = fma2(wreg[2 * j + 1], h.y, acc);
        }
        float2 p = up2(acc);
        hn = tanh_acc(p.x + p.y);
        outb[t * Hc + r] = hn;
        hbuf[((t + 1) & 1) * 256 + r] = hn;
        __syncthreads();
        pc = pn;
    }
    hlast[b * Hc + r] = hn;
}

__global__ void tail_kernel(const int* __restrict__ x, float* __restrict__ outSeq) {
    int i = threadIdx.x;
    outSeq[i] = (float)x[i * T2c + (T2c - 1)];
}

extern "C" void kernel_launch(void* const* d_in, const int* in_sizes, int n_in,
                              void* d_out, int out_size) {
    const int*   x    = (const int*)d_in[0];
    const float* tab  = (const float*)d_in[1];
    const float* Wih  = (const float*)d_in[2];
    const float* Whh  = (const float*)d_in[3];
    const float* bih  = (const float*)d_in[4];
    const float* bhh  = (const float*)d_in[5];
    const float* Wout = (const float*)d_in[6];
    const float* bout = (const float*)d_in[7];
    float* out = (float*)d_out;

    float *actA, *actB, *pre;
    __nv_bfloat16 *ahi, *alo, *whi, *wlo;
    cudaGetSymbolAddress((void**)&actA, g_actA);
    cudaGetSymbolAddress((void**)&actB, g_actB);
    cudaGetSymbolAddress((void**)&pre, g_pre);
    cudaGetSymbolAddress((void**)&ahi, g_ahi);
    cudaGetSymbolAddress((void**)&alo, g_alo);
    cudaGetSymbolAddress((void**)&whi, g_whi);
    cudaGetSymbolAddress((void**)&wlo, g_wlo);

    cudaFuncSetAttribute(rnn_scan, cudaFuncAttributeMaxDynamicSharedMemorySize, SCAN_SMEM);
    cudaFuncSetAttribute(mma_gemm, cudaFuncAttributeMaxDynamicSharedMemorySize, GEMM_SMEM);

    const size_t LOGITS = (size_t)Bc * Tc * Vc;
    float* lstate = out + LOGITS;
    float* seq = out + LOGITS + 2 * Bc * Hc;

    const int CONV_ACT = (Bc * Tc * Hc) / 1024;
    const int CONV_LW = (Hc * Ec) / 1024;
    const int CONV_WOUT = (Vc * Hc) / 1024;

    embed_kernel<<<Bc * Tc, 64>>>(x, tab, actA);

    dim3 blk(256);
    // layer 0
    conv_kernel<<<CONV_ACT, 256>>>(actA, ahi, alo);
    conv_kernel<<<CONV_LW, 256>>>(Wih, whi, wlo);
    mma_gemm<<<dim3(2, 256), blk, GEMM_SMEM>>>(ahi, alo, whi, wlo, bih, pre, Hc);
    rnn_scan<<<Bc, 256, SCAN_SMEM>>>(pre, Whh, bhh, actB, lstate);
    // layer 1
    conv_kernel<<<CONV_ACT, 256>>>(actB, ahi, alo);
    conv_kernel<<<CONV_LW, 256>>>(Wih + Hc * Ec, whi, wlo);
    mma_gemm<<<dim3(2, 256), blk, GEMM_SMEM>>>(ahi, alo, whi, wlo, bih + Hc, pre, Hc);
    rnn_scan<<<Bc, 256, SCAN_SMEM>>>(pre, Whh + Hc * Hc, bhh + Hc, actA, lstate + Bc * Hc);
    // output projection
    conv_kernel<<<CONV_ACT, 256>>>(actA, ahi, alo);
    conv_kernel<<<CONV_WOUT, 256>>>(Wout, whi, wlo);
    mma_gemm<<<dim3((Vc + 127) / 128, 256), blk, GEMM_SMEM>>>(ahi, alo, whi, wlo, bout, out, Vc);

    tail_kernel<<<1, Bc>>>(x, seq);
}

// round 5
// speedup vs baseline: 2.2346x; 1.0526x over previous
#include <cuda_runtime.h>
#include <cuda_fp16.h>
#include <cstdint>

typedef unsigned long long u64;
typedef unsigned int u32;

#define Bc 64
#define Tc 512
#define T2c 514
#define Ec 256
#define Hc 256
#define Vc 5000

// scratch (allocation-free rule: __device__ globals)
__device__ float g_pre[Bc * Tc * Hc];
__device__ __half g_ahi[Bc * Tc * Hc];
__device__ __half g_alo[Bc * Tc * Hc];
__device__ __half g_whi[Vc * Hc];

// ---------------- helpers ----------------
__device__ __forceinline__ u32 smem_u32(const void* p) {
    u32 a; asm("{ .reg .u64 t; cvta.to.shared.u64 t, %1; cvt.u32.u64 %0, t; }" : "=r"(a) : "l"(p));
    return a;
}
__device__ __forceinline__ u64 pk2(float x, float y) {
    u64 r; asm("mov.b64 %0,{%1,%2};" : "=l"(r) : "f"(x), "f"(y)); return r;
}
__device__ __forceinline__ u64 fma2(u64 a, u64 b, u64 c) {
    u64 d; asm("fma.rn.f32x2 %0,%1,%2,%3;" : "=l"(d) : "l"(a), "l"(b), "l"(c)); return d;
}
__device__ __forceinline__ float2 up2(u64 p) {
    float2 r; asm("mov.b64 {%0,%1},%2;" : "=f"(r.x), "=f"(r.y) : "l"(p)); return r;
}
__device__ __forceinline__ void ldsm_x4(u32* r, u32 addr) {
    asm volatile("ldmatrix.sync.aligned.m8n8.x4.shared.b16 {%0,%1,%2,%3}, [%4];"
                 : "=r"(r[0]), "=r"(r[1]), "=r"(r[2]), "=r"(r[3]) : "r"(addr));
}
__device__ __forceinline__ void mma_f16(float* d, const u32* a, const u32* b) {
    asm volatile(
        "mma.sync.aligned.m16n8k16.row.col.f32.f16.f16.f32 "
        "{%0,%1,%2,%3},{%4,%5,%6,%7},{%8,%9},{%0,%1,%2,%3};"
        : "+f"(d[0]), "+f"(d[1]), "+f"(d[2]), "+f"(d[3])
        : "r"(a[0]), "r"(a[1]), "r"(a[2]), "r"(a[3]), "r"(b[0]), "r"(b[1]));
}
__device__ __forceinline__ void cpa16(u32 dst, const void* src, u32 sz) {
    asm volatile("cp.async.cg.shared.global [%0], [%1], 16, %2;"
                 :: "r"(dst), "l"(src), "r"(sz) : "memory");
}
__device__ __forceinline__ void cp_commit() {
    asm volatile("cp.async.commit_group;" ::: "memory");
}
__device__ __forceinline__ float tanh_acc(float x) {
    float ax = fabsf(x);
    float e;
    asm("ex2.approx.f32 %0, %1;" : "=f"(e) : "f"(-2.885390082f * ax)); // exp(-2|x|)
    float denom;
    asm("rcp.approx.f32 %0, %1;" : "=f"(denom) : "f"(1.0f + e));
    float t = (1.0f - e) * denom;
    return copysignf(t, x);
}

// ---------------- embedding gather -> fp16 hi/lo ----------------
__global__ void embed_kernel(const int* __restrict__ x, const float* __restrict__ tab,
                             __half* __restrict__ hi, __half* __restrict__ lo) {
    int bt = blockIdx.x;
    int b = bt >> 9, t = bt & 511;
    int tok = x[b * T2c + t];
    float4 v = reinterpret_cast<const float4*>(tab + (size_t)tok * Ec)[threadIdx.x];
    __half h0 = __float2half_rn(v.x), h1 = __float2half_rn(v.y);
    __half h2 = __float2half_rn(v.z), h3 = __float2half_rn(v.w);
    __half l0 = __float2half_rn(v.x - __half2float(h0));
    __half l1 = __float2half_rn(v.y - __half2float(h1));
    __half l2 = __float2half_rn(v.z - __half2float(h2));
    __half l3 = __float2half_rn(v.w - __half2float(h3));
    size_t o = (size_t)bt * Ec + threadIdx.x * 4;
    *reinterpret_cast<ushort4*>(hi + o) = make_ushort4(
        __half_as_ushort(h0), __half_as_ushort(h1), __half_as_ushort(h2), __half_as_ushort(h3));
    *reinterpret_cast<ushort4*>(lo + o) = make_ushort4(
        __half_as_ushort(l0), __half_as_ushort(l1), __half_as_ushort(l2), __half_as_ushort(l3));
}

// ---------------- fp32 weights -> plain fp16 ----------------
__global__ void convw_kernel(const float* __restrict__ src, __half* __restrict__ dst) {
    size_t i = ((size_t)blockIdx.x * 256 + threadIdx.x) * 4;
    float4 v = *reinterpret_cast<const float4*>(src + i);
    *reinterpret_cast<ushort4*>(dst + i) = make_ushort4(
        __half_as_ushort(__float2half_rn(v.x)), __half_as_ushort(__float2half_rn(v.y)),
        __half_as_ushort(__float2half_rn(v.z)), __half_as_ushort(__float2half_rn(v.w)));
}

// ---------------- HMMA fp16 2-term GEMM ----------------
// C = (Ahi+Alo) * Bh^T + bias. CTA 128x128, warps 2(M)x4(N), warp tile 64x32.
// 3-stage cp.async ring, one __syncthreads per chunk. Row stride 40 halfs (80B).
#define TILE_B 10240            // 128 rows * 80 bytes
#define STAGE_B (3 * TILE_B)    // Ahi | Alo | Bh
#define GEMM_SMEM (3 * STAGE_B) // 92160

__global__ void __launch_bounds__(256, 2) mma_gemm(
    const __half* __restrict__ Ahi, const __half* __restrict__ Alo,
    const __half* __restrict__ Bh,
    const float* __restrict__ bias, float* __restrict__ C, int Nact)
{
    extern __shared__ __align__(16) char smem[];
    const u32 sb = smem_u32(smem);
    const int tid = threadIdx.x;
    const int wid = tid >> 5, lane = tid & 31;
    const int m0 = blockIdx.y * 128, n0 = blockIdx.x * 128;
    const int wm = (wid >> 2) * 64, wn = (wid & 3) * 32;

    const int row0 = tid >> 2, seg0 = tid & 3;
    const int row1 = (tid + 256) >> 2, seg1 = (tid + 256) & 3;

    float acc[4][4][4];
#pragma unroll
    for (int i = 0; i < 4; i++)
#pragma unroll
        for (int j = 0; j < 4; j++)
#pragma unroll
            for (int q = 0; q < 4; q++) acc[i][j][q] = 0.f;

    auto load_chunk = [&](int k0, int stage) {
        const u32 base = sb + stage * STAGE_B;
#pragma unroll
        for (int h = 0; h < 2; h++) {
            const int row = h ? row1 : row0;
            const int seg = h ? seg1 : seg0;
            const u32 dst = base + row * 80 + seg * 16;
            const size_t aoff = (size_t)(m0 + row) * 256 + k0 + seg * 8;
            cpa16(dst, Ahi + aoff, 16);
            cpa16(dst + TILE_B, Alo + aoff, 16);
            const int br = n0 + row;
            const u32 sz = (br < Nact) ? 16u : 0u;
            const int brc = (br < Nact) ? br : (Nact - 1);
            cpa16(dst + 2 * TILE_B, Bh + (size_t)brc * 256 + k0 + seg * 8, sz);
        }
        cp_commit();
    };

    // ldmatrix lane addresses (relative, bytes)
    const u32 arow = (wm + (lane & 15)) * 80 + (lane >> 4) * 16;
    const u32 brow = (wn + (lane & 7) + ((lane >> 4) & 1) * 8) * 80 + ((lane >> 3) & 1) * 16;

    load_chunk(0, 0);
    load_chunk(32, 1);

#pragma unroll 1
    for (int ic = 0; ic < 8; ic++) {
        if (ic < 7) asm volatile("cp.async.wait_group 1;" ::: "memory");
        else        asm volatile("cp.async.wait_group 0;" ::: "memory");
        __syncthreads();
        if (ic < 6) load_chunk((ic + 2) * 32, (ic + 2) % 3);

        const u32 base = sb + (ic % 3) * STAGE_B;
        const u32 aHi = base, aLo = base + TILE_B, bHm = base + 2 * TILE_B;
#pragma unroll
        for (int kk = 0; kk < 2; kk++) {
            u32 af[4][4], bf[2][4];
#pragma unroll
            for (int jb = 0; jb < 2; jb++)
                ldsm_x4(bf[jb], bHm + brow + jb * 16 * 80 + kk * 32);
#pragma unroll
            for (int im = 0; im < 4; im++)
                ldsm_x4(af[im], aHi + arow + im * 16 * 80 + kk * 32);
#pragma unroll
            for (int im = 0; im < 4; im++)
#pragma unroll
                for (int jn = 0; jn < 4; jn++)
                    mma_f16(acc[im][jn], af[im], &bf[jn >> 1][(jn & 1) * 2]);
#pragma unroll
            for (int im = 0; im < 4; im++)
                ldsm_x4(af[im], aLo + arow + im * 16 * 80 + kk * 32);
#pragma unroll
            for (int im = 0; im < 4; im++)
#pragma unroll
                for (int jn = 0; jn < 4; jn++)
                    mma_f16(acc[im][jn], af[im], &bf[jn >> 1][(jn & 1) * 2]);
        }
    }

    // epilogue
    const int rbase = m0 + wm + (lane >> 2);
    const int cbase = n0 + wn + (lane & 3) * 2;
#pragma unroll
    for (int im = 0; im < 4; im++) {
#pragma unroll
        for (int jn = 0; jn < 4; jn++) {
            int n = cbase + jn * 8;
            if (n < Nact) {
                float bx = bias[n], by = bias[n + 1];
                int r0 = rbase + im * 16;
                *reinterpret_cast<float2*>(C + (size_t)r0 * Nact + n) =
                    make_float2(acc[im][jn][0] + bx, acc[im][jn][1] + by);
                *reinterpret_cast<float2*>(C + (size_t)(r0 + 8) * Nact + n) =
                    make_float2(acc[im][jn][2] + bx, acc[im][jn][3] + by);
            }
        }
    }
}

// ---------------- recurrence v3 ----------------
// h_t = tanh(pre[t] + Whh h_{t-1} + b). 1 CTA/batch, 256 threads (1 row each).
// k[0,64) weights in smem (transposed, conflict-free LDS.128); k[64,256) in 96 u64 regs.
// 4 accumulator chains for ILP. h double-buffered -> 1 barrier/step. pre prefetched.
// Emits fp16 hi/lo directly for the next GEMM.
#define KS4 16
#define SCAN_SMEM (KS4 * 256 * 16 + 2 * 256 * 4)
__global__ void __launch_bounds__(256, 1) rnn_scan(
    const float* __restrict__ pre, const float* __restrict__ Whh,
    const float* __restrict__ bhh, __half* __restrict__ outhi, __half* __restrict__ outlo,
    float* __restrict__ hlast)
{
    extern __shared__ __align__(16) float sm[];
    float4* w4 = reinterpret_cast<float4*>(sm);
    float* hbuf = sm + KS4 * 256 * 4;
    const int b = blockIdx.x, r = threadIdx.x;

#pragma unroll
    for (int k4 = 0; k4 < KS4; k4++)
        w4[k4 * 256 + r] = *reinterpret_cast<const float4*>(&Whh[r * 256 + k4 * 4]);

    u64 wreg[96];
#pragma unroll
    for (int j = 0; j < 48; j++) {
        ulonglong2 v = *reinterpret_cast<const ulonglong2*>(&Whh[r * 256 + 64 + j * 4]);
        wreg[2 * j] = v.x; wreg[2 * j + 1] = v.y;
    }
    const float bias = bhh[r];
    hbuf[r] = 0.f;
    __syncthreads();

    const float* preb = pre + (size_t)b * Tc * Hc;
    __half* ohi = outhi + (size_t)b * Tc * Hc;
    __half* olo = outlo + (size_t)b * Tc * Hc;
    const ulonglong2* w2s = reinterpret_cast<const ulonglong2*>(sm);

    float pc = preb[r];
    float hn = 0.f;
#pragma unroll 1
    for (int t = 0; t < Tc; t++) {
        int tn = (t + 1 < Tc) ? t + 1 : t;
        float pn = preb[tn * Hc + r];
        const ulonglong2* hc = reinterpret_cast<const ulonglong2*>(hbuf + (t & 1) * 256);
        u64 a0 = pk2(pc + bias, 0.f), a1 = 0ull, a2 = 0ull, a3 = 0ull;
#pragma unroll
        for (int k4 = 0; k4 < KS4; k4++) {
            ulonglong2 w = w2s[k4 * 256 + r];
            ulonglong2 h = hc[k4];
            a0 = fma2(w.x, h.x, a0);
            a0 = fma2(w.y, h.y, a0);
        }
#pragma unroll
        for (int j = 0; j < 16; j++) {
            ulonglong2 h = hc[KS4 + j];
            a1 = fma2(wreg[2 * j], h.x, a1);
            a1 = fma2(wreg[2 * j + 1], h.y, a1);
        }
#pragma unroll
        for (int j = 16; j < 32; j++) {
            ulonglong2 h = hc[KS4 + j];
            a2 = fma2(wreg[2 * j], h.x, a2);
            a2 = fma2(wreg[2 * j + 1], h.y, a2);
        }
#pragma unroll
        for (int j = 32; j < 48; j++) {
            ulonglong2 h = hc[KS4 + j];
            a3 = fma2(wreg[2 * j], h.x, a3);
            a3 = fma2(wreg[2 * j + 1], h.y, a3);
        }
        float2 p0 = up2(a0), p1 = up2(a1), p2 = up2(a2), p3 = up2(a3);
        hn = tanh_acc(((p0.x + p0.y) + (p1.x + p1.y)) + ((p2.x + p2.y) + (p3.x + p3.y)));
        __half hh = __float2half_rn(hn);
        __half hl = __float2half_rn(hn - __half2float(hh));
        ohi[t * Hc + r] = hh;
        olo[t * Hc + r] = hl;
        hbuf[((t + 1) & 1) * 256 + r] = hn;
        __syncthreads();
        pc = pn;
    }
    hlast[b * Hc + r] = hn;
}

__global__ void tail_kernel(const int* __restrict__ x, float* __restrict__ outSeq) {
    int i = threadIdx.x;
    outSeq[i] = (float)x[i * T2c + (T2c - 1)];
}

extern "C" void kernel_launch(void* const* d_in, const int* in_sizes, int n_in,
                              void* d_out, int out_size) {
    const int*   x    = (const int*)d_in[0];
    const float* tab  = (const float*)d_in[1];
    const float* Wih  = (const float*)d_in[2];
    const float* Whh  = (const float*)d_in[3];
    const float* bih  = (const float*)d_in[4];
    const float* bhh  = (const float*)d_in[5];
    const float* Wout = (const float*)d_in[6];
    const float* bout = (const float*)d_in[7];
    float* out = (float*)d_out;

    float* pre;
    __half *ahi, *alo, *whi;
    cudaGetSymbolAddress((void**)&pre, g_pre);
    cudaGetSymbolAddress((void**)&ahi, g_ahi);
    cudaGetSymbolAddress((void**)&alo, g_alo);
    cudaGetSymbolAddress((void**)&whi, g_whi);

    cudaFuncSetAttribute(rnn_scan, cudaFuncAttributeMaxDynamicSharedMemorySize, SCAN_SMEM);
    cudaFuncSetAttribute(mma_gemm, cudaFuncAttributeMaxDynamicSharedMemorySize, GEMM_SMEM);

    const size_t LOGITS = (size_t)Bc * Tc * Vc;
    float* lstate = out + LOGITS;
    float* seq = out + LOGITS + 2 * Bc * Hc;

    embed_kernel<<<Bc * Tc, 64>>>(x, tab, ahi, alo);

    dim3 blk(256);
    // layer 0
    convw_kernel<<<(Hc * Ec) / 1024, 256>>>(Wih, whi);
    mma_gemm<<<dim3(2, 256), blk, GEMM_SMEM>>>(ahi, alo, whi, bih, pre, Hc);
    rnn_scan<<<Bc, 256, SCAN_SMEM>>>(pre, Whh, bhh, ahi, alo, lstate);
    // layer 1
    convw_kernel<<<(Hc * Ec) / 1024, 256>>>(Wih + Hc * Ec, whi);
    mma_gemm<<<dim3(2, 256), blk, GEMM_SMEM>>>(ahi, alo, whi, bih + Hc, pre, Hc);
    rnn_scan<<<Bc, 256, SCAN_SMEM>>>(pre, Whh + Hc * Hc, bhh + Hc, ahi, alo, lstate + Bc * Hc);
    // output projection
    convw_kernel<<<(Vc * Hc) / 1024, 256>>>(Wout, whi);
    mma_gemm<<<dim3((Vc + 127) / 128, 256), blk, GEMM_SMEM>>>(ahi, alo, whi, bout, out, Vc);

    tail_kernel<<<1, Bc>>>(x, seq);
}